// round 4
// baseline (speedup 1.0000x reference)
#include <cuda_runtime.h>
#include <math.h>

#define BATCH 4096
#define CDIM 32
#define PDIM 196
#define ENC 512
#define ATTD 128
#define NTHR 224   // 7 warps, covers 196 positions

// scratch (allocation-free rule: __device__ globals, referenced directly from device code)
__device__ float g_Uh[BATCH * ATTD];  // U_h = hidden @ U_w^T + U_b
__device__ float g_bz[BATCH * CDIM];  // pre-sigmoid beta

// ---- f32x2 helpers (sm_103a packed fp32; FFMA2 only reachable via PTX) ----
__device__ __forceinline__ unsigned long long pk2(float lo, float hi) {
    unsigned long long r;
    asm("mov.b64 %0, {%1, %2};" : "=l"(r) : "f"(lo), "f"(hi));
    return r;
}
__device__ __forceinline__ void upk2(float& lo, float& hi, unsigned long long v) {
    asm("mov.b64 {%0, %1}, %2;" : "=f"(lo), "=f"(hi) : "l"(v));
}
__device__ __forceinline__ unsigned long long fma2(unsigned long long a,
                                                   unsigned long long b,
                                                   unsigned long long c) {
    unsigned long long d;
    asm("fma.rn.f32x2 %0, %1, %2, %3;" : "=l"(d) : "l"(a), "l"(b), "l"(c));
    return d;
}
__device__ __forceinline__ unsigned long long add2(unsigned long long a,
                                                   unsigned long long b) {
    unsigned long long d;
    asm("add.rn.f32x2 %0, %1, %2;" : "=l"(d) : "l"(a), "l"(b));
    return d;
}
__device__ __forceinline__ float ex2f(float x) {
    float y; asm("ex2.approx.f32 %0, %1;" : "=f"(y) : "f"(x)); return y;
}
__device__ __forceinline__ float rcpf(float x) {
    float y; asm("rcp.approx.f32 %0, %1;" : "=f"(y) : "f"(x)); return y;
}

// ---------------------------------------------------------------------------
// Kernel 1: out[b][j] = sum_k hidden[b][k] * W[j][k] + bias[j]
// DST selects the __device__ scratch buffer (0 -> g_Uh, 1 -> g_bz).
// ---------------------------------------------------------------------------
template <int N, int TN, int DST>
__global__ void __launch_bounds__(256) gemm_hidden(
    const float* __restrict__ A,    // [BATCH, ENC]
    const float* __restrict__ W,    // [N, ENC]
    const float* __restrict__ bias) // [N]
{
    constexpr int BM = 32, BK = 16, TM = 4;
    constexpr int NCG = N / TN;
    static_assert(NCG * (BM / TM) == 256, "thread layout");

    float* __restrict__ out = (DST == 0) ? g_Uh : g_bz;

    __shared__ float Asm[BK][BM];
    __shared__ float Bsm[BK][N];

    const int tid = threadIdx.x;
    const int b0 = blockIdx.x * BM;
    const int rg = tid / NCG;
    const int cg = tid % NCG;

    float acc[TM][TN];
#pragma unroll
    for (int i = 0; i < TM; i++)
#pragma unroll
        for (int j = 0; j < TN; j++) acc[i][j] = 0.f;

    for (int k0 = 0; k0 < ENC; k0 += BK) {
        if (tid < 128) {
            int row = tid >> 2, kq = tid & 3;
            float4 v = *(const float4*)(A + (size_t)(b0 + row) * ENC + k0 + 4 * kq);
            Asm[4 * kq + 0][row] = v.x;
            Asm[4 * kq + 1][row] = v.y;
            Asm[4 * kq + 2][row] = v.z;
            Asm[4 * kq + 3][row] = v.w;
        }
        for (int i = tid; i < N * 4; i += 256) {
            int j = i >> 2, kq = i & 3;
            float4 v = *(const float4*)(W + (size_t)j * ENC + k0 + 4 * kq);
            Bsm[4 * kq + 0][j] = v.x;
            Bsm[4 * kq + 1][j] = v.y;
            Bsm[4 * kq + 2][j] = v.z;
            Bsm[4 * kq + 3][j] = v.w;
        }
        __syncthreads();

#pragma unroll
        for (int k = 0; k < BK; k++) {
            float a[TM];
            *(float4*)a = *(const float4*)&Asm[k][rg * TM];
            float bb[TN];
            if (TN == 4) {
                *(float4*)bb = *(const float4*)&Bsm[k][cg * TN];
            } else {
#pragma unroll
                for (int j = 0; j < TN; j++) bb[j] = Bsm[k][cg * TN + j];
            }
#pragma unroll
            for (int i = 0; i < TM; i++)
#pragma unroll
                for (int j = 0; j < TN; j++) acc[i][j] += a[i] * bb[j];
        }
        __syncthreads();
    }

#pragma unroll
    for (int i = 0; i < TM; i++) {
        int row = b0 + rg * TM + i;
#pragma unroll
        for (int j = 0; j < TN; j++) {
            int col = cg * TN + j;
            out[(size_t)row * N + col] = acc[i][j] + bias[col];
        }
    }
}

// ---------------------------------------------------------------------------
// Kernel 2: per-batch attention. 1 block = 1 batch element, 224 threads.
// score(p) = vb + sum_a v_a * tanh( dot(img_p, Ww_a) + Uh_a + Wb_a )
// tanh(t) = 1 - 2/(e^{2t}+1), with sum(v) and -2v prefolded.
// ---------------------------------------------------------------------------
__global__ void __launch_bounds__(NTHR) attn_kernel(
    const float* __restrict__ img,  // [B, 32, 196]
    const float* __restrict__ Ww,   // [128, 32]
    const float* __restrict__ Wb,   // [128]
    const float* __restrict__ vw,   // [128]
    const float* __restrict__ vb,   // [1]
    float* __restrict__ ctx_out,    // [B, 32]
    float* __restrict__ att_out)    // [B, 196]
{
    const int b = blockIdx.x;
    const int tid = threadIdx.x;
    const int lane = tid & 31;
    const int wid = tid >> 5;

    __shared__ ulonglong2 Wsm[ATTD][8];              // W_w rows, pair-packed (16KB)
    __shared__ unsigned long long spk[ATTD];         // pack(Uh + Wb, 0)
    __shared__ float vm2[ATTD];                      // -2 * v
    __shared__ __align__(16) float score[NTHR];
    __shared__ float red[8];
    __shared__ float svinit, smax, ssum;

    // stage W_w (byte-identical copy; row-major pairs line up with img pairs)
    {
        const float4* Ww4 = (const float4*)Ww;
        float4* Wf = (float4*)Wsm;
        for (int i = tid; i < ATTD * 8; i += NTHR) Wf[i] = Ww4[i];
    }
    float myv = 0.f;
    if (tid < ATTD) {
        float v = vw[tid];
        vm2[tid] = -2.f * v;
        myv = v;
        float sb = g_Uh[(size_t)b * ATTD + tid] + Wb[tid];
        spk[tid] = pk2(sb, 0.f);
    }
    // block-reduce sum(v) -> svinit = vb + sum(v)
    {
        float s = myv;
#pragma unroll
        for (int off = 16; off > 0; off >>= 1)
            s += __shfl_xor_sync(0xffffffffu, s, off);
        if (lane == 0) red[wid] = s;
    }
    __syncthreads();
    if (tid == 0) {
        float t = vb[0];
#pragma unroll
        for (int w = 0; w < NTHR / 32; w++) t += red[w];
        svinit = t;
    }
    __syncthreads();

    // --- per-position score ---
    float sc;
    if (tid < PDIM) {
        const float* ib = img + (size_t)b * CDIM * PDIM + tid;
        float im[CDIM];
#pragma unroll
        for (int c = 0; c < CDIM; c++) im[c] = ib[c * PDIM];  // coalesced
        unsigned long long imk[CDIM / 2];
#pragma unroll
        for (int q = 0; q < CDIM / 2; q++) imk[q] = pk2(im[2 * q], im[2 * q + 1]);

        sc = svinit;
#pragma unroll 4
        for (int a = 0; a < ATTD; a++) {
            unsigned long long acc[4];
            acc[0] = spk[a];
            acc[1] = 0ull; acc[2] = 0ull; acc[3] = 0ull;
#pragma unroll
            for (int q = 0; q < 8; q++) {
                ulonglong2 w = Wsm[a][q];  // broadcast across warp
                acc[(2 * q) & 3]     = fma2(imk[2 * q],     w.x, acc[(2 * q) & 3]);
                acc[(2 * q + 1) & 3] = fma2(imk[2 * q + 1], w.y, acc[(2 * q + 1) & 3]);
            }
            acc[0] = add2(acc[0], acc[1]);
            acc[2] = add2(acc[2], acc[3]);
            acc[0] = add2(acc[0], acc[2]);
            float lo, hi;
            upk2(lo, hi, acc[0]);
            float t = lo + hi;
            // tanh(t) = 1 - 2*rcp(exp2(t*2*log2(e)) + 1); the "1" lives in svinit fold
            float e = ex2f(t * 2.885390081777927f);
            float r = rcpf(e + 1.f);
            sc = fmaf(vm2[a], r, sc);
        }
    } else {
        sc = -1e30f;
    }
    score[tid] = sc;
    __syncthreads();

    // --- softmax over 196 positions ---
    float m = sc;
#pragma unroll
    for (int off = 16; off > 0; off >>= 1)
        m = fmaxf(m, __shfl_xor_sync(0xffffffffu, m, off));
    if (lane == 0) red[wid] = m;
    __syncthreads();
    if (tid == 0) {
        float v = red[0];
#pragma unroll
        for (int w = 1; w < NTHR / 32; w++) v = fmaxf(v, red[w]);
        smax = v;
    }
    __syncthreads();

    float e = (tid < PDIM) ? ex2f((sc - smax) * 1.44269504088896f) : 0.f;
    float s = e;
#pragma unroll
    for (int off = 16; off > 0; off >>= 1)
        s += __shfl_xor_sync(0xffffffffu, s, off);
    if (lane == 0) red[wid] = s;
    __syncthreads();
    if (tid == 0) {
        float v = 0.f;
#pragma unroll
        for (int w = 0; w < NTHR / 32; w++) v += red[w];
        ssum = v;
    }
    __syncthreads();

    float w = e * rcpf(ssum);
    if (tid < PDIM) att_out[(size_t)b * PDIM + tid] = w;
    score[tid] = w;  // normalized weights (0 for tid>=196)
    __syncthreads();

    // --- context: warp 0, lane = channel c ---
    if (tid < CDIM) {
        const float4* ib4 = (const float4*)(img + (size_t)b * CDIM * PDIM + tid * PDIM);
        const float4* w4 = (const float4*)score;
        float a0 = 0.f, a1 = 0.f, a2 = 0.f, a3 = 0.f;
#pragma unroll
        for (int q = 0; q < PDIM / 4; q++) {  // 49 float4 = exactly 196
            float4 iv = ib4[q];
            float4 wv = w4[q];
            a0 += iv.x * wv.x;
            a1 += iv.y * wv.y;
            a2 += iv.z * wv.z;
            a3 += iv.w * wv.w;
        }
        float ctx = (a0 + a1) + (a2 + a3);
        float z = g_bz[(size_t)b * CDIM + tid];
        float beta = rcpf(1.f + ex2f(-z * 1.44269504088896f));
        ctx_out[(size_t)b * CDIM + tid] = ctx * beta;
    }
}

// ---------------------------------------------------------------------------
// launch — kernel launches only, nothing else
// ---------------------------------------------------------------------------
extern "C" void kernel_launch(void* const* d_in, const int* in_sizes, int n_in,
                              void* d_out, int out_size)
{
    const float* img    = (const float*)d_in[0];
    const float* hidden = (const float*)d_in[1];
    const float* Ww     = (const float*)d_in[2];
    const float* Wb     = (const float*)d_in[3];
    const float* Uw     = (const float*)d_in[4];
    const float* Ub     = (const float*)d_in[5];
    const float* vw     = (const float*)d_in[6];
    const float* vb     = (const float*)d_in[7];
    const float* fbw    = (const float*)d_in[8];
    const float* fbb    = (const float*)d_in[9];

    float* ctx = (float*)d_out;                          // [B, 32]
    float* att = (float*)d_out + (size_t)BATCH * CDIM;   // [B, 196]

    gemm_hidden<ATTD, 4, 0><<<BATCH / 32, 256>>>(hidden, Uw, Ub);
    gemm_hidden<CDIM, 1, 1><<<BATCH / 32, 256>>>(hidden, fbw, fbb);
    attn_kernel<<<BATCH, NTHR>>>(img, Ww, Wb, vw, vb, ctx, att);
}

// round 9
// speedup vs baseline: 1.2341x; 1.2341x over previous
#include <cuda_runtime.h>
#include <math.h>

#define BATCH 4096
#define CDIM 32
#define PDIM 196
#define ENC 512
#define ATTD 128
#define NTHR 224          // 7 warps covers 196 positions
#define TWO_LOG2E 2.885390081777927f
#define LOG2E 1.4426950408889634f

// scratch (allocation-free rule: __device__ globals)
__device__ float g_Uh[BATCH * ATTD];  // U_h = hidden @ U_w^T + U_b
__device__ float g_bz[BATCH * CDIM];  // pre-sigmoid beta

// ---- f32x2 helpers (FFMA2 only reachable via PTX) ----
__device__ __forceinline__ unsigned long long pk2(float lo, float hi) {
    unsigned long long r;
    asm("mov.b64 %0, {%1, %2};" : "=l"(r) : "f"(lo), "f"(hi));
    return r;
}
__device__ __forceinline__ void upk2(float& lo, float& hi, unsigned long long v) {
    asm("mov.b64 {%0, %1}, %2;" : "=f"(lo), "=f"(hi) : "l"(v));
}
__device__ __forceinline__ unsigned long long fma2(unsigned long long a,
                                                   unsigned long long b,
                                                   unsigned long long c) {
    unsigned long long d;
    asm("fma.rn.f32x2 %0, %1, %2, %3;" : "=l"(d) : "l"(a), "l"(b), "l"(c));
    return d;
}
__device__ __forceinline__ unsigned long long add2(unsigned long long a,
                                                   unsigned long long b) {
    unsigned long long d;
    asm("add.rn.f32x2 %0, %1, %2;" : "=l"(d) : "l"(a), "l"(b));
    return d;
}
__device__ __forceinline__ float ex2f(float x) {
    float y; asm("ex2.approx.f32 %0, %1;" : "=f"(y) : "f"(x)); return y;
}
__device__ __forceinline__ float rcpf(float x) {
    float y; asm("rcp.approx.f32 %0, %1;" : "=f"(y) : "f"(x)); return y;
}

// ---------------------------------------------------------------------------
// Fused hidden GEMMs: out[b][j] = sum_k hidden[b][k] * W[j][k] + bias[j]
// blockIdx.y==0 -> N=128 into g_Uh ; blockIdx.y==1 -> N=32 into g_bz
// BM=32, BK=16, thread tile TM=4 x TN. Padded smem (Asm stride 36, Bsm 132)
// keeps float4 reads 16B-aligned while de-aliasing banks across k-rows.
// ---------------------------------------------------------------------------
template <int N, int TN>
__device__ __forceinline__ void gemm_body(
    const float* __restrict__ A, const float* __restrict__ W,
    const float* __restrict__ bias, float* __restrict__ out,
    float (*Asm)[36], float (*Bsm)[132])
{
    constexpr int BM = 32, BK = 16, TM = 4;
    constexpr int NCG = N / TN;   // 32 for both instantiations
    static_assert(NCG * (BM / TM) == 256, "thread layout");

    const int tid = threadIdx.x;
    const int b0 = blockIdx.x * BM;
    const int rg = tid / NCG;
    const int cg = tid % NCG;

    float acc[TM][TN];
#pragma unroll
    for (int i = 0; i < TM; i++)
#pragma unroll
        for (int j = 0; j < TN; j++) acc[i][j] = 0.f;

    for (int k0 = 0; k0 < ENC; k0 += BK) {
        if (tid < 128) {
            int row = tid >> 2, kq = tid & 3;
            float4 v = *(const float4*)(A + (size_t)(b0 + row) * ENC + k0 + 4 * kq);
            Asm[4 * kq + 0][row] = v.x;
            Asm[4 * kq + 1][row] = v.y;
            Asm[4 * kq + 2][row] = v.z;
            Asm[4 * kq + 3][row] = v.w;
        }
#pragma unroll 1
        for (int i = tid; i < N * 4; i += 256) {
            int j = i >> 2, kq = i & 3;
            float4 v = *(const float4*)(W + (size_t)j * ENC + k0 + 4 * kq);
            Bsm[4 * kq + 0][j] = v.x;
            Bsm[4 * kq + 1][j] = v.y;
            Bsm[4 * kq + 2][j] = v.z;
            Bsm[4 * kq + 3][j] = v.w;
        }
        __syncthreads();

#pragma unroll
        for (int k = 0; k < BK; k++) {
            float a[TM];
            *(float4*)a = *(const float4*)&Asm[k][rg * TM];
            float bb[TN];
            if (TN == 4) {
                *(float4*)bb = *(const float4*)&Bsm[k][cg * TN];
            } else {
#pragma unroll
                for (int j = 0; j < TN; j++) bb[j] = Bsm[k][cg * TN + j];
            }
#pragma unroll
            for (int i = 0; i < TM; i++)
#pragma unroll
                for (int j = 0; j < TN; j++) acc[i][j] += a[i] * bb[j];
        }
        __syncthreads();
    }

#pragma unroll
    for (int i = 0; i < TM; i++) {
        int row = b0 + rg * TM + i;
#pragma unroll
        for (int j = 0; j < TN; j++) {
            int col = cg * TN + j;
            out[(size_t)row * N + col] = acc[i][j] + bias[col];
        }
    }
}

__global__ void __launch_bounds__(256, 2) gemm_fused(
    const float* __restrict__ hidden,
    const float* __restrict__ Uw, const float* __restrict__ Ub,
    const float* __restrict__ fbw, const float* __restrict__ fbb)
{
    __shared__ float Asm[16][36];
    __shared__ float Bsm[16][132];
    if (blockIdx.y == 0)
        gemm_body<ATTD, 4>(hidden, Uw, Ub, g_Uh, Asm, Bsm);
    else
        gemm_body<CDIM, 1>(hidden, fbw, fbb, g_bz, Asm, Bsm);
}

// ---------------------------------------------------------------------------
// Attention: 1 block = 2 batch elements, 224 threads (thread = position p).
// score(p) = vb + sum_a v_a * tanh( dot(img_p, Ww_a) + Uh_a + Wb_a )
// tanh(t) = 1 - 2/(e^{2t}+1); sum(v), -2v, and the 2*log2e scale prefolded.
// Each Wsm[a] LDS.128 feeds FMAs for BOTH batches (halves LDS traffic).
// ---------------------------------------------------------------------------
__global__ void __launch_bounds__(NTHR, 2) attn_kernel(
    const float* __restrict__ img,  // [B, 32, 196]
    const float* __restrict__ Ww,   // [128, 32]
    const float* __restrict__ Wb,   // [128]
    const float* __restrict__ vw,   // [128]
    const float* __restrict__ vb,   // [1]
    float* __restrict__ ctx_out,    // [B, 32]
    float* __restrict__ att_out)    // [B, 196]
{
    const int b0 = blockIdx.x * 2;
    const int b1 = b0 + 1;
    const int tid = threadIdx.x;
    const int lane = tid & 31;
    const int wid = tid >> 5;

    __shared__ ulonglong2 Wsm[ATTD][8];          // W_w rows pair-packed (16KB)
    __shared__ float sbp0[ATTD], sbp1[ATTD];     // (Uh+Wb)*2log2e per batch
    __shared__ float vm2[ATTD];                  // -2 * v
    __shared__ __align__(16) float score0[NTHR];
    __shared__ __align__(16) float score1[NTHR];
    __shared__ float red0[7], red1[7];
    __shared__ float svinit, sm0, sm1, ss0, ss1;

    {
        const float4* Ww4 = (const float4*)Ww;
        float4* Wf = (float4*)Wsm;
        for (int i = tid; i < ATTD * 8; i += NTHR) Wf[i] = Ww4[i];
    }
    float myv = 0.f;
    if (tid < ATTD) {
        float v = vw[tid];
        vm2[tid] = -2.f * v;
        myv = v;
        float wb = Wb[tid];
        sbp0[tid] = (g_Uh[(size_t)b0 * ATTD + tid] + wb) * TWO_LOG2E;
        sbp1[tid] = (g_Uh[(size_t)b1 * ATTD + tid] + wb) * TWO_LOG2E;
    }
    {
        float s = myv;
#pragma unroll
        for (int off = 16; off > 0; off >>= 1)
            s += __shfl_xor_sync(0xffffffffu, s, off);
        if (lane == 0) red0[wid] = s;
    }
    __syncthreads();
    if (tid == 0) {
        float t = vb[0];
#pragma unroll
        for (int w = 0; w < NTHR / 32; w++) t += red0[w];
        svinit = t;
    }
    __syncthreads();

    // --- per-position scores for both batches ---
    float sc0, sc1;
    if (tid < PDIM) {
        const float* ib0 = img + ((size_t)b0 * CDIM) * PDIM + tid;
        const float* ib1 = img + ((size_t)b1 * CDIM) * PDIM + tid;
        unsigned long long imk0[CDIM / 2], imk1[CDIM / 2];
#pragma unroll
        for (int q = 0; q < CDIM / 2; q++) {
            imk0[q] = pk2(ib0[(2 * q) * PDIM], ib0[(2 * q + 1) * PDIM]);
            imk1[q] = pk2(ib1[(2 * q) * PDIM], ib1[(2 * q + 1) * PDIM]);
        }

        sc0 = svinit;
        sc1 = svinit;
#pragma unroll 4
        for (int a = 0; a < ATTD; a++) {
            unsigned long long a00 = 0ull, a01 = 0ull, a10 = 0ull, a11 = 0ull;
#pragma unroll
            for (int q = 0; q < 8; q++) {
                ulonglong2 w = Wsm[a][q];   // one LDS.128 broadcast, 4 FMA2
                a00 = fma2(imk0[2 * q], w.x, a00);
                a01 = fma2(imk0[2 * q + 1], w.y, a01);
                a10 = fma2(imk1[2 * q], w.x, a10);
                a11 = fma2(imk1[2 * q + 1], w.y, a11);
            }
            float lo, hi, d0, d1;
            a00 = add2(a00, a01);
            upk2(lo, hi, a00); d0 = lo + hi;
            a10 = add2(a10, a11);
            upk2(lo, hi, a10); d1 = lo + hi;
            // e = exp(2t) via ex2; bias (pre-scaled) folded into the fma
            float e0 = ex2f(fmaf(d0, TWO_LOG2E, sbp0[a]));
            float e1 = ex2f(fmaf(d1, TWO_LOG2E, sbp1[a]));
            float vm = vm2[a];
            sc0 = fmaf(vm, rcpf(e0 + 1.f), sc0);
            sc1 = fmaf(vm, rcpf(e1 + 1.f), sc1);
        }
    } else {
        sc0 = -1e30f;
        sc1 = -1e30f;
    }

    // --- softmax (both batches) ---
    float m0 = sc0, m1 = sc1;
#pragma unroll
    for (int off = 16; off > 0; off >>= 1) {
        m0 = fmaxf(m0, __shfl_xor_sync(0xffffffffu, m0, off));
        m1 = fmaxf(m1, __shfl_xor_sync(0xffffffffu, m1, off));
    }
    if (lane == 0) { red0[wid] = m0; red1[wid] = m1; }
    __syncthreads();
    if (tid == 0) {
        float v0 = red0[0], v1 = red1[0];
#pragma unroll
        for (int w = 1; w < NTHR / 32; w++) {
            v0 = fmaxf(v0, red0[w]);
            v1 = fmaxf(v1, red1[w]);
        }
        sm0 = v0; sm1 = v1;
    }
    __syncthreads();

    float e0 = (tid < PDIM) ? ex2f((sc0 - sm0) * LOG2E) : 0.f;
    float e1 = (tid < PDIM) ? ex2f((sc1 - sm1) * LOG2E) : 0.f;
    float s0 = e0, s1 = e1;
#pragma unroll
    for (int off = 16; off > 0; off >>= 1) {
        s0 += __shfl_xor_sync(0xffffffffu, s0, off);
        s1 += __shfl_xor_sync(0xffffffffu, s1, off);
    }
    if (lane == 0) { red0[wid] = s0; red1[wid] = s1; }
    __syncthreads();
    if (tid == 0) {
        float v0 = 0.f, v1 = 0.f;
#pragma unroll
        for (int w = 0; w < NTHR / 32; w++) { v0 += red0[w]; v1 += red1[w]; }
        ss0 = v0; ss1 = v1;
    }
    __syncthreads();

    float w0 = e0 * rcpf(ss0);
    float w1 = e1 * rcpf(ss1);
    if (tid < PDIM) {
        att_out[(size_t)b0 * PDIM + tid] = w0;
        att_out[(size_t)b1 * PDIM + tid] = w1;
    }
    score0[tid] = w0;   // zero for tid >= PDIM
    score1[tid] = w1;
    __syncthreads();

    // --- context: warp 0 -> batch b0, warp 1 -> batch b1 (lane = channel) ---
    if (wid < 2) {
        const int b = (wid == 0) ? b0 : b1;
        const float* sw = (wid == 0) ? score0 : score1;
        const float4* ib4 = (const float4*)(img + ((size_t)b * CDIM + lane) * PDIM);
        const float4* w4 = (const float4*)sw;
        float a0 = 0.f, a1 = 0.f, a2 = 0.f, a3 = 0.f;
#pragma unroll
        for (int q = 0; q < PDIM / 4; q++) {   // 49 float4 = exactly 196
            float4 iv = ib4[q];
            float4 wv = w4[q];
            a0 += iv.x * wv.x;
            a1 += iv.y * wv.y;
            a2 += iv.z * wv.z;
            a3 += iv.w * wv.w;
        }
        float ctx = (a0 + a1) + (a2 + a3);
        float z = g_bz[(size_t)b * CDIM + lane];
        float beta = rcpf(1.f + ex2f(-z * LOG2E));
        ctx_out[(size_t)b * CDIM + lane] = ctx * beta;
    }
}

// ---------------------------------------------------------------------------
// launch — kernel launches only
// ---------------------------------------------------------------------------
extern "C" void kernel_launch(void* const* d_in, const int* in_sizes, int n_in,
                              void* d_out, int out_size)
{
    const float* img    = (const float*)d_in[0];
    const float* hidden = (const float*)d_in[1];
    const float* Ww     = (const float*)d_in[2];
    const float* Wb     = (const float*)d_in[3];
    const float* Uw     = (const float*)d_in[4];
    const float* Ub     = (const float*)d_in[5];
    const float* vw     = (const float*)d_in[6];
    const float* vb     = (const float*)d_in[7];
    const float* fbw    = (const float*)d_in[8];
    const float* fbb    = (const float*)d_in[9];

    float* ctx = (float*)d_out;                          // [B, 32]
    float* att = (float*)d_out + (size_t)BATCH * CDIM;   // [B, 196]

    gemm_fused<<<dim3(BATCH / 32, 2), 256>>>(hidden, Uw, Ub, fbw, fbb);
    attn_kernel<<<BATCH / 2, NTHR>>>(img, Ww, Wb, vw, vb, ctx, att);
}

// round 13
// speedup vs baseline: 1.8614x; 1.5084x over previous
#include <cuda_runtime.h>
#include <cstdint>

#define BATCH 4096
#define CDIM 32
#define PDIM 196
#define ENC 512
#define ATTD 128
#define LOG2E 1.4426950408889634f

#define ATTN_GRID 296      // 2 CTAs/SM x 148
#define NTHR 256           // 8 warps
#define NPAD 200           // padded position count (25 n-tiles of 8)
#define ROWF 36            // img_s row stride in floats (bank de-aliasing, 16B aligned)

// scratch (allocation-free rule: __device__ globals)
__device__ float g_Uh[BATCH * ATTD];
__device__ float g_bz[BATCH * CDIM];

// ---------------- helpers ----------------
__device__ __forceinline__ uint32_t tf32c(float x) {
    uint32_t y; asm("cvt.rna.tf32.f32 %0, %1;" : "=r"(y) : "f"(x)); return y;
}
__device__ __forceinline__ float tanha(float x) {
    float y; asm("tanh.approx.f32 %0, %1;" : "=f"(y) : "f"(x)); return y;
}
__device__ __forceinline__ float ex2f(float x) {
    float y; asm("ex2.approx.f32 %0, %1;" : "=f"(y) : "f"(x)); return y;
}
__device__ __forceinline__ float rcpf(float x) {
    float y; asm("rcp.approx.f32 %0, %1;" : "=f"(y) : "f"(x)); return y;
}
// D[16x8] += A[16x8(tf32)] * B[8x8(tf32)]
__device__ __forceinline__ void mma16n8k8(float* d, const uint32_t* a,
                                          uint32_t b0, uint32_t b1) {
    asm volatile(
        "mma.sync.aligned.m16n8k8.row.col.f32.tf32.tf32.f32 "
        "{%0,%1,%2,%3}, {%4,%5,%6,%7}, {%8,%9}, {%0,%1,%2,%3};"
        : "+f"(d[0]), "+f"(d[1]), "+f"(d[2]), "+f"(d[3])
        : "r"(a[0]), "r"(a[1]), "r"(a[2]), "r"(a[3]), "r"(b0), "r"(b1));
}

// ---------------------------------------------------------------------------
// Hidden GEMMs (round-9-style, BM=16): out[b][j] = hidden[b] . W[j] + bias[j]
// ---------------------------------------------------------------------------
template <int N, int TN>
__device__ __forceinline__ void gemm_body(
    const float* __restrict__ A, const float* __restrict__ W,
    const float* __restrict__ bias, float* __restrict__ out,
    float (*Asm)[18], float (*Bsm)[132])
{
    constexpr int BM = 16, BK = 16, TM = 2;
    constexpr int NCG = N / TN;   // 32
    static_assert(NCG * (BM / TM) == 256, "layout");

    const int tid = threadIdx.x;
    const int b0 = blockIdx.x * BM;
    const int rg = tid / NCG;     // 0..7
    const int cg = tid % NCG;

    float acc[TM][TN];
#pragma unroll
    for (int i = 0; i < TM; i++)
#pragma unroll
        for (int j = 0; j < TN; j++) acc[i][j] = 0.f;

    for (int k0 = 0; k0 < ENC; k0 += BK) {
        if (tid < 64) {
            int row = tid >> 2, kq = tid & 3;
            float4 v = *(const float4*)(A + (size_t)(b0 + row) * ENC + k0 + 4 * kq);
            Asm[4 * kq + 0][row] = v.x;
            Asm[4 * kq + 1][row] = v.y;
            Asm[4 * kq + 2][row] = v.z;
            Asm[4 * kq + 3][row] = v.w;
        }
#pragma unroll 1
        for (int i = tid; i < N * 4; i += 256) {
            int j = i >> 2, kq = i & 3;
            float4 v = *(const float4*)(W + (size_t)j * ENC + k0 + 4 * kq);
            Bsm[4 * kq + 0][j] = v.x;
            Bsm[4 * kq + 1][j] = v.y;
            Bsm[4 * kq + 2][j] = v.z;
            Bsm[4 * kq + 3][j] = v.w;
        }
        __syncthreads();

#pragma unroll
        for (int k = 0; k < BK; k++) {
            float2 a = *(const float2*)&Asm[k][rg * TM];
            float bb[TN];
            if (TN == 4) {
                *(float4*)bb = *(const float4*)&Bsm[k][cg * TN];
            } else {
#pragma unroll
                for (int j = 0; j < TN; j++) bb[j] = Bsm[k][cg * TN + j];
            }
#pragma unroll
            for (int j = 0; j < TN; j++) {
                acc[0][j] += a.x * bb[j];
                acc[1][j] += a.y * bb[j];
            }
        }
        __syncthreads();
    }

#pragma unroll
    for (int i = 0; i < TM; i++) {
        int row = b0 + rg * TM + i;
#pragma unroll
        for (int j = 0; j < TN; j++) {
            int col = cg * TN + j;
            out[(size_t)row * N + col] = acc[i][j] + bias[col];
        }
    }
}

__global__ void __launch_bounds__(256, 3) gemm_fused(
    const float* __restrict__ hidden,
    const float* __restrict__ Uw, const float* __restrict__ Ub,
    const float* __restrict__ fbw, const float* __restrict__ fbb)
{
    __shared__ float Asm[16][18];
    __shared__ float Bsm[16][132];
    if (blockIdx.y == 0)
        gemm_body<ATTD, 4>(hidden, Uw, Ub, g_Uh, Asm, Bsm);
    else
        gemm_body<CDIM, 1>(hidden, fbw, fbb, g_bz, Asm, Bsm);
}

// ---------------------------------------------------------------------------
// Attention: persistent CTAs, warp-level tf32 mma.sync score GEMM.
// D[a, p] = sum_c Ww[a,c] * img[b][c][p]; warp w owns a in [16w, 16w+16).
// ---------------------------------------------------------------------------
__global__ void __launch_bounds__(NTHR, 2) attn_kernel(
    const float* __restrict__ img,  // [B, 32, 196]
    const float* __restrict__ Ww,   // [128, 32]
    const float* __restrict__ Wb,   // [128]
    const float* __restrict__ vw,   // [128]
    const float* __restrict__ vb,   // [1]
    float* __restrict__ ctx_out,    // [B, 32]
    float* __restrict__ att_out)    // [B, 196]
{
    __shared__ float img_s[NPAD][ROWF];            // transposed img, exact f32
    __shared__ float scpart[8][NPAD];              // per-warp score partials
    __shared__ __align__(16) float score[NTHR];
    __shared__ float red[8];
    __shared__ float s_max, s_sum;

    const int tid = threadIdx.x;
    const int lane = tid & 31;
    const int wid = tid >> 5;
    const int g = lane >> 2;          // row group 0..7
    const int q = lane & 3;           // col group 0..3

    // zero pad rows 196..199 (only ever written here; read as zeros each batch)
    for (int i = tid; i < (NPAD - PDIM) * ROWF; i += NTHR)
        img_s[PDIM + i / ROWF][i % ROWF] = 0.f;

    // stationary A-fragments: Ww rows for this thread, tf32, held in registers
    const int a0r = 16 * wid + g;
    const int a1r = a0r + 8;
    uint32_t afr[4][4];
#pragma unroll
    for (int kk = 0; kk < 4; kk++) {
        afr[kk][0] = tf32c(Ww[a0r * CDIM + 8 * kk + q]);
        afr[kk][1] = tf32c(Ww[a1r * CDIM + 8 * kk + q]);
        afr[kk][2] = tf32c(Ww[a0r * CDIM + 8 * kk + q + 4]);
        afr[kk][3] = tf32c(Ww[a1r * CDIM + 8 * kk + q + 4]);
    }
    const float v0 = vw[a0r], v1 = vw[a1r];
    const float wb0 = Wb[a0r], wb1 = Wb[a1r];
    const float vbv = vb[0];

    for (int b = blockIdx.x; b < BATCH; b += ATTN_GRID) {
        // per-batch bias for this thread's two attention rows
        const float sb0 = g_Uh[(size_t)b * ATTD + a0r] + wb0;
        const float sb1 = g_Uh[(size_t)b * ATTD + a1r] + wb1;

        // img transpose -> img_s[p][c] (coalesced LDG across p; STS.128 conflict-free)
        if (tid < PDIM) {
            const float* ib = img + (size_t)b * CDIM * PDIM + tid;
#pragma unroll
            for (int qq = 0; qq < 8; qq++) {
                float4 t;
                t.x = ib[(4 * qq + 0) * PDIM];
                t.y = ib[(4 * qq + 1) * PDIM];
                t.z = ib[(4 * qq + 2) * PDIM];
                t.w = ib[(4 * qq + 3) * PDIM];
                *(float4*)&img_s[tid][4 * qq] = t;
            }
        }
        __syncthreads();

        // --- score GEMM + fused tanh/v-dot epilogue ---
        const int prow = g;   // within n-tile, b-frag col = g
#pragma unroll 1
        for (int nt = 0; nt < NPAD / 8; nt++) {     // 25 n-tiles
            float d[4] = {0.f, 0.f, 0.f, 0.f};
            const float* brow = img_s[8 * nt + prow];
#pragma unroll
            for (int kk = 0; kk < 4; kk++) {
                uint32_t b0f = tf32c(brow[8 * kk + q]);
                uint32_t b1f = tf32c(brow[8 * kk + q + 4]);
                mma16n8k8(d, afr[kk], b0f, b1f);
            }
            // tanh + v-weighted sum over this warp's 16 a-rows
            float t00 = tanha(d[0] + sb0);
            float t01 = tanha(d[1] + sb0);
            float t10 = tanha(d[2] + sb1);
            float t11 = tanha(d[3] + sb1);
            float s0 = fmaf(v0, t00, v1 * t10);   // col p = 8nt + 2q
            float s1 = fmaf(v0, t01, v1 * t11);   // col p = 8nt + 2q + 1
            // reduce over row groups g (lane bits 2..4)
#pragma unroll
            for (int off = 4; off <= 16; off <<= 1) {
                s0 += __shfl_xor_sync(0xffffffffu, s0, off);
                s1 += __shfl_xor_sync(0xffffffffu, s1, off);
            }
            if (g == 0) {
                float2 pr; pr.x = s0; pr.y = s1;
                *(float2*)&scpart[wid][8 * nt + 2 * q] = pr;
            }
        }
        __syncthreads();

        // --- total score + softmax over 196 positions ---
        float sc;
        {
            const int pi = (tid < NPAD) ? tid : 0;
            float acc = vbv;
#pragma unroll
            for (int w = 0; w < 8; w++) acc += scpart[w][pi];
            sc = (tid < PDIM) ? acc : -1e30f;
        }
        float m = sc;
#pragma unroll
        for (int off = 16; off > 0; off >>= 1)
            m = fmaxf(m, __shfl_xor_sync(0xffffffffu, m, off));
        if (lane == 0) red[wid] = m;
        __syncthreads();
        if (tid == 0) {
            float v = red[0];
#pragma unroll
            for (int w = 1; w < 8; w++) v = fmaxf(v, red[w]);
            s_max = v;
        }
        __syncthreads();

        float e = (tid < PDIM) ? ex2f((sc - s_max) * LOG2E) : 0.f;
        float s = e;
#pragma unroll
        for (int off = 16; off > 0; off >>= 1)
            s += __shfl_xor_sync(0xffffffffu, s, off);
        if (lane == 0) red[wid] = s;
        __syncthreads();
        if (tid == 0) {
            float v = 0.f;
#pragma unroll
            for (int w = 0; w < 8; w++) v += red[w];
            s_sum = v;
        }
        __syncthreads();

        float w = e * rcpf(s_sum);
        if (tid < PDIM) att_out[(size_t)b * PDIM + tid] = w;
        score[tid] = w;   // zero for tid >= PDIM
        __syncthreads();

        // --- context from exact-f32 img_s: 8 threads per channel ---
        {
            const int c = tid >> 3;   // 0..31
            const int j = tid & 7;
            float acc = 0.f;
#pragma unroll 7
            for (int p = j; p < PDIM; p += 8)
                acc += img_s[p][c] * score[p];
            acc += __shfl_xor_sync(0xffffffffu, acc, 1);
            acc += __shfl_xor_sync(0xffffffffu, acc, 2);
            acc += __shfl_xor_sync(0xffffffffu, acc, 4);
            if (j == 0) {
                float z = g_bz[(size_t)b * CDIM + c];
                float beta = rcpf(1.f + ex2f(-z * LOG2E));
                ctx_out[(size_t)b * CDIM + c] = acc * beta;
            }
        }
        __syncthreads();   // img_s/score reused next iteration
    }
}

// ---------------------------------------------------------------------------
extern "C" void kernel_launch(void* const* d_in, const int* in_sizes, int n_in,
                              void* d_out, int out_size)
{
    const float* img    = (const float*)d_in[0];
    const float* hidden = (const float*)d_in[1];
    const float* Ww     = (const float*)d_in[2];
    const float* Wb     = (const float*)d_in[3];
    const float* Uw     = (const float*)d_in[4];
    const float* Ub     = (const float*)d_in[5];
    const float* vw     = (const float*)d_in[6];
    const float* vb     = (const float*)d_in[7];
    const float* fbw    = (const float*)d_in[8];
    const float* fbb    = (const float*)d_in[9];

    float* ctx = (float*)d_out;                          // [B, 32]
    float* att = (float*)d_out + (size_t)BATCH * CDIM;   // [B, 196]

    gemm_fused<<<dim3(BATCH / 16, 2), 256>>>(hidden, Uw, Ub, fbw, fbb);
    attn_kernel<<<ATTN_GRID, NTHR>>>(img, Ww, Wb, vw, vb, ctx, att);
}

// round 16
// speedup vs baseline: 2.0646x; 1.1091x over previous
#include <cuda_runtime.h>
#include <cstdint>

#define BATCH 4096
#define CDIM 32
#define PDIM 196
#define ENC 512
#define ATTD 128
#define LOG2E 1.4426950408889634f

#define ATTN_GRID 296      // 2 CTAs/SM x 148
#define NTHR 256           // 8 warps
#define NPAD 200           // padded positions (25 n-tiles of 8)
#define ROWF 36            // smem row stride in floats (bank de-alias, 16B-aligned rows)

// scratch (allocation-free rule: __device__ globals)
__device__ float g_Uh[BATCH * ATTD];
__device__ float g_bz[BATCH * CDIM];

// ---------------- helpers ----------------
__device__ __forceinline__ uint32_t tf32c(float x) {
    uint32_t y; asm("cvt.rna.tf32.f32 %0, %1;" : "=r"(y) : "f"(x)); return y;
}
__device__ __forceinline__ float tf32f(float x) {
    uint32_t y; asm("cvt.rna.tf32.f32 %0, %1;" : "=r"(y) : "f"(x));
    return __uint_as_float(y);
}
__device__ __forceinline__ float tanha(float x) {
    float y; asm("tanh.approx.f32 %0, %1;" : "=f"(y) : "f"(x)); return y;
}
__device__ __forceinline__ float ex2f(float x) {
    float y; asm("ex2.approx.f32 %0, %1;" : "=f"(y) : "f"(x)); return y;
}
__device__ __forceinline__ float rcpf(float x) {
    float y; asm("rcp.approx.f32 %0, %1;" : "=f"(y) : "f"(x)); return y;
}
// D[16x8] += A[16x8(tf32)] * B[8x8(tf32)]
__device__ __forceinline__ void mma16n8k8(float* d, const uint32_t* a,
                                          uint32_t b0, uint32_t b1) {
    asm volatile(
        "mma.sync.aligned.m16n8k8.row.col.f32.tf32.tf32.f32 "
        "{%0,%1,%2,%3}, {%4,%5,%6,%7}, {%8,%9}, {%0,%1,%2,%3};"
        : "+f"(d[0]), "+f"(d[1]), "+f"(d[2]), "+f"(d[3])
        : "r"(a[0]), "r"(a[1]), "r"(a[2]), "r"(a[3]), "r"(b0), "r"(b1));
}

// ---------------------------------------------------------------------------
// tf32 mma hidden GEMM: out[b][n] = sum_k A[b][k] * W[n][k] + bias[n]
// K processed in chunks of 32; within a chunk, k-index i of mma-step kk maps
// to channel ch(i,kk) = i<4 ? 8i+2kk : 8(i-4)+2kk+1, making every fragment
// load a contiguous 8-float block (2x LDS.128).
// ---------------------------------------------------------------------------
template <int N, int BM, int WROWS, int WCOLS>
__device__ __forceinline__ void gemm_tf32_body(
    const float* __restrict__ A, const float* __restrict__ W,
    const float* __restrict__ bias, float* __restrict__ out, float* smem)
{
    constexpr int MF = BM / WROWS / 16;   // m-frags per warp
    constexpr int NF = N / WCOLS / 8;     // n-frags per warp
    static_assert(WROWS * WCOLS == 8, "8 warps");

    float (*A_s)[ROWF] = (float(*)[ROWF])smem;
    float (*B_s)[ROWF] = (float(*)[ROWF])(smem + BM * ROWF);

    const int tid = threadIdx.x;
    const int lane = tid & 31, wid = tid >> 5;
    const int g = lane >> 2, q = lane & 3;
    const int wm = (wid / WCOLS) * (BM / WROWS);
    const int wn = (wid % WCOLS) * (N / WCOLS);
    const int brow0 = blockIdx.x * BM;

    float acc[MF][NF][4];
#pragma unroll
    for (int mf = 0; mf < MF; mf++)
#pragma unroll
        for (int nf = 0; nf < NF; nf++)
#pragma unroll
            for (int i = 0; i < 4; i++) acc[mf][nf][i] = 0.f;

    for (int k0 = 0; k0 < ENC; k0 += 32) {
        // stage A tile [BM x 32] as tf32
#pragma unroll
        for (int i = tid; i < BM * 8; i += 256) {
            int r = i >> 3, c4 = (i & 7) * 4;
            float4 v = *(const float4*)(A + (size_t)(brow0 + r) * ENC + k0 + c4);
            float4 t;
            t.x = tf32f(v.x); t.y = tf32f(v.y); t.z = tf32f(v.z); t.w = tf32f(v.w);
            *(float4*)&A_s[r][c4] = t;
        }
        // stage W tile [N x 32] as tf32
#pragma unroll
        for (int i = tid; i < N * 8; i += 256) {
            int r = i >> 3, c4 = (i & 7) * 4;
            float4 v = *(const float4*)(W + (size_t)r * ENC + k0 + c4);
            float4 t;
            t.x = tf32f(v.x); t.y = tf32f(v.y); t.z = tf32f(v.z); t.w = tf32f(v.w);
            *(float4*)&B_s[r][c4] = t;
        }
        __syncthreads();

        // a-fragments: rows (g, g+8) of each m-frag, channels 8q..8q+7
        uint32_t au[MF][2][8];
#pragma unroll
        for (int mf = 0; mf < MF; mf++) {
#pragma unroll
            for (int h = 0; h < 2; h++) {
                const float* ar = &A_s[wm + 16 * mf + g + 8 * h][8 * q];
                *(uint4*)&au[mf][h][0] = *(const uint4*)&ar[0];
                *(uint4*)&au[mf][h][4] = *(const uint4*)&ar[4];
            }
        }
#pragma unroll
        for (int nf = 0; nf < NF; nf++) {
            uint32_t bu[8];
            const float* br = &B_s[wn + 8 * nf + g][8 * q];
            *(uint4*)&bu[0] = *(const uint4*)&br[0];
            *(uint4*)&bu[4] = *(const uint4*)&br[4];
#pragma unroll
            for (int mf = 0; mf < MF; mf++) {
#pragma unroll
                for (int kk = 0; kk < 4; kk++) {
                    uint32_t af[4] = {au[mf][0][2 * kk], au[mf][1][2 * kk],
                                      au[mf][0][2 * kk + 1], au[mf][1][2 * kk + 1]};
                    mma16n8k8(acc[mf][nf], af, bu[2 * kk], bu[2 * kk + 1]);
                }
            }
        }
        __syncthreads();
    }

    // epilogue: add bias, store (STG.64)
#pragma unroll
    for (int mf = 0; mf < MF; mf++) {
#pragma unroll
        for (int nf = 0; nf < NF; nf++) {
            int col = wn + 8 * nf + 2 * q;
            float b0 = bias[col], b1 = bias[col + 1];
            int row = brow0 + wm + 16 * mf + g;
            float2 v0; v0.x = acc[mf][nf][0] + b0; v0.y = acc[mf][nf][1] + b1;
            float2 v1; v1.x = acc[mf][nf][2] + b0; v1.y = acc[mf][nf][3] + b1;
            *(float2*)&out[(size_t)row * N + col] = v0;
            *(float2*)&out[(size_t)(row + 8) * N + col] = v1;
        }
    }
}

__global__ void __launch_bounds__(256) gemm_fused(
    const float* __restrict__ hidden,
    const float* __restrict__ Uw, const float* __restrict__ Ub,
    const float* __restrict__ fbw, const float* __restrict__ fbb)
{
    __shared__ float smem[(64 + 128) * ROWF];   // fits both configs
    if (blockIdx.y == 0) {
        // U_h: N=128, BM=64, warps 2x4 -> grid.x = 64
        gemm_tf32_body<ATTD, 64, 2, 4>(hidden, Uw, Ub, g_Uh, smem);
    } else {
        // beta pre-act: N=32, BM=128, warps 8x1 -> grid.x = 32
        if (blockIdx.x >= BATCH / 128) return;
        gemm_tf32_body<CDIM, 128, 8, 1>(hidden, fbw, fbb, g_bz, smem);
    }
}

// ---------------------------------------------------------------------------
// Attention: persistent CTAs. img_s holds tf32-rounded transposed img; warp w
// owns att rows [16w, 16w+16). Context re-reads exact img from gmem (L1-hot).
// ---------------------------------------------------------------------------
__global__ void __launch_bounds__(NTHR, 2) attn_kernel(
    const float* __restrict__ img,  // [B, 32, 196]
    const float* __restrict__ Ww,   // [128, 32]
    const float* __restrict__ Wb,   // [128]
    const float* __restrict__ vw,   // [128]
    const float* __restrict__ vb,   // [1]
    float* __restrict__ ctx_out,    // [B, 32]
    float* __restrict__ att_out)    // [B, 196]
{
    __shared__ __align__(16) float img_s[NPAD][ROWF];   // tf32-rounded
    __shared__ float scpart[8][NPAD];
    __shared__ __align__(16) float score[NTHR];
    __shared__ float red[8];
    __shared__ float s_max, s_sum;

    const int tid = threadIdx.x;
    const int lane = tid & 31;
    const int wid = tid >> 5;
    const int g = lane >> 2;          // row group 0..7
    const int q = lane & 3;           // col group 0..3

    // zero pad rows 196..199 once
    for (int i = tid; i < (NPAD - PDIM) * ROWF; i += NTHR)
        img_s[PDIM + i / ROWF][i % ROWF] = 0.f;

    // stationary A-frags: Ww rows (16w+g, +8), permuted channels, tf32 in regs
    const int a0r = 16 * wid + g;
    const int a1r = a0r + 8;
    uint32_t afr[4][4];
#pragma unroll
    for (int kk = 0; kk < 4; kk++) {
        afr[kk][0] = tf32c(Ww[a0r * CDIM + 8 * q + 2 * kk]);
        afr[kk][1] = tf32c(Ww[a1r * CDIM + 8 * q + 2 * kk]);
        afr[kk][2] = tf32c(Ww[a0r * CDIM + 8 * q + 2 * kk + 1]);
        afr[kk][3] = tf32c(Ww[a1r * CDIM + 8 * q + 2 * kk + 1]);
    }
    const float v0 = vw[a0r], v1 = vw[a1r];
    const float wb0 = Wb[a0r], wb1 = Wb[a1r];
    const float vbv = vb[0];

    for (int b = blockIdx.x; b < BATCH; b += ATTN_GRID) {
        const float sb0 = g_Uh[(size_t)b * ATTD + a0r] + wb0;
        const float sb1 = g_Uh[(size_t)b * ATTD + a1r] + wb1;

        // img transpose -> img_s[p][c], tf32-rounded (coalesced LDG across p)
        if (tid < PDIM) {
            const float* ib = img + (size_t)b * CDIM * PDIM + tid;
#pragma unroll
            for (int qq = 0; qq < 8; qq++) {
                float4 t;
                t.x = tf32f(ib[(4 * qq + 0) * PDIM]);
                t.y = tf32f(ib[(4 * qq + 1) * PDIM]);
                t.z = tf32f(ib[(4 * qq + 2) * PDIM]);
                t.w = tf32f(ib[(4 * qq + 3) * PDIM]);
                *(float4*)&img_s[tid][4 * qq] = t;
            }
        }
        __syncthreads();

        // --- score GEMM + fused tanh/v-dot epilogue ---
#pragma unroll 1
        for (int nt = 0; nt < NPAD / 8; nt++) {     // 25 n-tiles
            // b-frag: this thread's channels 8q..8q+7 at position row 8nt+g
            uint32_t bu[8];
            const float* br = &img_s[8 * nt + g][8 * q];
            *(uint4*)&bu[0] = *(const uint4*)&br[0];
            *(uint4*)&bu[4] = *(const uint4*)&br[4];

            float d[4] = {0.f, 0.f, 0.f, 0.f};
#pragma unroll
            for (int kk = 0; kk < 4; kk++)
                mma16n8k8(d, afr[kk], bu[2 * kk], bu[2 * kk + 1]);

            float t00 = tanha(d[0] + sb0);
            float t01 = tanha(d[1] + sb0);
            float t10 = tanha(d[2] + sb1);
            float t11 = tanha(d[3] + sb1);
            float s0 = fmaf(v0, t00, v1 * t10);   // position 8nt + 2q
            float s1 = fmaf(v0, t01, v1 * t11);   // position 8nt + 2q + 1
#pragma unroll
            for (int off = 4; off <= 16; off <<= 1) {
                s0 += __shfl_xor_sync(0xffffffffu, s0, off);
                s1 += __shfl_xor_sync(0xffffffffu, s1, off);
            }
            if (g == 0) {
                float2 pr; pr.x = s0; pr.y = s1;
                *(float2*)&scpart[wid][8 * nt + 2 * q] = pr;
            }
        }
        __syncthreads();

        // --- total score + softmax over 196 positions ---
        float sc;
        {
            const int pi = (tid < NPAD) ? tid : 0;
            float acc = vbv;
#pragma unroll
            for (int w = 0; w < 8; w++) acc += scpart[w][pi];
            sc = (tid < PDIM) ? acc : -1e30f;
        }
        float m = sc;
#pragma unroll
        for (int off = 16; off > 0; off >>= 1)
            m = fmaxf(m, __shfl_xor_sync(0xffffffffu, m, off));
        if (lane == 0) red[wid] = m;
        __syncthreads();
        if (tid == 0) {
            float v = red[0];
#pragma unroll
            for (int w = 1; w < 8; w++) v = fmaxf(v, red[w]);
            s_max = v;
        }
        __syncthreads();

        float e = (tid < PDIM) ? ex2f((sc - s_max) * LOG2E) : 0.f;
        float s = e;
#pragma unroll
        for (int off = 16; off > 0; off >>= 1)
            s += __shfl_xor_sync(0xffffffffu, s, off);
        if (lane == 0) red[wid] = s;
        __syncthreads();
        if (tid == 0) {
            float v = 0.f;
#pragma unroll
            for (int w = 0; w < 8; w++) v += red[w];
            s_sum = v;
        }
        __syncthreads();

        float w = e * rcpf(s_sum);
        if (tid < PDIM) att_out[(size_t)b * PDIM + tid] = w;
        score[tid] = w;   // zero for tid >= PDIM
        __syncthreads();

        // --- context from gmem img (exact f32, L1-hot): 8 threads/channel ---
        {
            const int c = tid >> 3;   // 0..31
            const int j = tid & 7;
            const float* ib = img + ((size_t)b * CDIM + c) * PDIM;
            float acc = 0.f;
            for (int p = j; p < PDIM; p += 8)
                acc += ib[p] * score[p];
            acc += __shfl_xor_sync(0xffffffffu, acc, 1);
            acc += __shfl_xor_sync(0xffffffffu, acc, 2);
            acc += __shfl_xor_sync(0xffffffffu, acc, 4);
            if (j == 0) {
                float z = g_bz[(size_t)b * CDIM + c];
                float beta = rcpf(1.f + ex2f(-z * LOG2E));
                ctx_out[(size_t)b * CDIM + c] = acc * beta;
            }
        }
        __syncthreads();   // img_s/score reused next iteration
    }
}

// ---------------------------------------------------------------------------
extern "C" void kernel_launch(void* const* d_in, const int* in_sizes, int n_in,
                              void* d_out, int out_size)
{
    const float* img    = (const float*)d_in[0];
    const float* hidden = (const float*)d_in[1];
    const float* Ww     = (const float*)d_in[2];
    const float* Wb     = (const float*)d_in[3];
    const float* Uw     = (const float*)d_in[4];
    const float* Ub     = (const float*)d_in[5];
    const float* vw     = (const float*)d_in[6];
    const float* vb     = (const float*)d_in[7];
    const float* fbw    = (const float*)d_in[8];
    const float* fbb    = (const float*)d_in[9];

    float* ctx = (float*)d_out;                          // [B, 32]
    float* att = (float*)d_out + (size_t)BATCH * CDIM;   // [B, 196]

    gemm_fused<<<dim3(BATCH / 64, 2), 256>>>(hidden, Uw, Ub, fbw, fbb);
    attn_kernel<<<ATTN_GRID, NTHR>>>(img, Ww, Wb, vw, vb, ctx, att);
}